// round 4
// baseline (speedup 1.0000x reference)
#include <cuda_runtime.h>

#define H       2048
#define E       64
#define M_TILE  64
#define K_TILE  32
#define NTHREADS 256

// Prep-kernel outputs (static device scratch; no allocations allowed)
__device__ float g_wgT[H * E];   // [h][e] = gate[e][h] * ln_weight[h]
__device__ float g_c[E];         // sum_h gate[e][h]*w[h]
__device__ float g_d[E];         // sum_h ln_bias[h]*gate[e][h]

// ---------------------------------------------------------------------------
// prep: build transposed, ln_weight-folded gate matrix + per-expert constants
// ---------------------------------------------------------------------------
__global__ void prep_kernel(const float* __restrict__ gate,
                            const float* __restrict__ w,
                            const float* __restrict__ b) {
    int e = blockIdx.x;
    int t = threadIdx.x;
    float sc = 0.f, sd = 0.f;
    for (int h = t; h < H; h += 256) {
        float gv = gate[e * H + h];
        float p  = gv * w[h];
        g_wgT[h * E + e] = p;
        sc += p;
        sd += b[h] * gv;
    }
    __shared__ float rs[256], rd[256];
    rs[t] = sc; rd[t] = sd;
    __syncthreads();
    for (int s = 128; s > 0; s >>= 1) {
        if (t < s) { rs[t] += rs[t + s]; rd[t] += rd[t + s]; }
        __syncthreads();
    }
    if (t == 0) { g_c[e] = rs[0]; g_d[e] = rd[0]; }
}

// packed f32x2 FMA (Blackwell): d = a*b + d elementwise on float pairs
__device__ __forceinline__ void ffma2(unsigned long long& d,
                                      unsigned long long a,
                                      unsigned long long b) {
    asm("fma.rn.f32x2 %0, %1, %2, %0;" : "+l"(d) : "l"(a), "l"(b));
}

// ---------------------------------------------------------------------------
// main: fused stats + GEMM + softmax + top2
// grid = n_rows/64 blocks, 256 threads; thread tile = 2 rows x 8 experts
// experts per thread: {tx*4..tx*4+3} U {32+tx*4..32+tx*4+3}  (contiguous 16B
// chunks across the warp's 8 tx groups -> 1-wavefront LDS for weights)
// ---------------------------------------------------------------------------
__global__ __launch_bounds__(NTHREADS)
void router_kernel(const float* __restrict__ X, float* __restrict__ out,
                   int n_rows) {
    __shared__ float s_xd[K_TILE][2 * M_TILE];  // x duplicated pairs: 16 KB
    __shared__ float s_w[K_TILE * E];           // 8 KB
    __shared__ float s_mu[M_TILE], s_rstd[M_TILE];
    __shared__ float s_c[E], s_d[E];

    const int t  = threadIdx.x;
    const int row_base = blockIdx.x * M_TILE;
    const int tx  = t & 7;       // expert group (0..7)
    const int tyg = t >> 3;      // row group (0..31)
    const int elo = tx * 4;      // low expert chunk base
    const int r0  = tyg * 2;     // 2 rows per thread

    if (t < E) { s_c[t] = g_c[t]; s_d[t] = g_d[t]; }

    // loader mapping: 4 threads per row, 8 consecutive floats each
    const int lrow = t >> 2;          // 0..63
    const int lk   = (t & 3) * 8;     // 0,8,16,24
    const float4* xg = (const float4*)(X + (size_t)(row_base + lrow) * H + lk);
    const float4* wg = (const float4*)g_wgT;   // tile kt starts at float4 idx kt*512

    float4 xr[2], wr[2];
#pragma unroll
    for (int i = 0; i < 2; i++) xr[i] = xg[i];
#pragma unroll
    for (int i = 0; i < 2; i++) wr[i] = wg[t + 256 * i];

    unsigned long long acc[2][4];
#pragma unroll
    for (int j = 0; j < 2; j++)
#pragma unroll
        for (int p = 0; p < 4; p++) acc[j][p] = 0ull;

    float sum = 0.f, sumsq = 0.f;

    const int NT = H / K_TILE;  // 64
    for (int kt = 0; kt < NT; ++kt) {
        // row stats from the registers we're about to store
#pragma unroll
        for (int i = 0; i < 2; i++) {
            sum   += xr[i].x + xr[i].y + xr[i].z + xr[i].w;
            sumsq += xr[i].x * xr[i].x + xr[i].y * xr[i].y +
                     xr[i].z * xr[i].z + xr[i].w * xr[i].w;
        }
        __syncthreads();
        // store x duplicated (k-transposed)
#pragma unroll
        for (int i = 0; i < 2; i++) {
            int kb = lk + 4 * i;
            *(float2*)&s_xd[kb + 0][2 * lrow] = make_float2(xr[i].x, xr[i].x);
            *(float2*)&s_xd[kb + 1][2 * lrow] = make_float2(xr[i].y, xr[i].y);
            *(float2*)&s_xd[kb + 2][2 * lrow] = make_float2(xr[i].z, xr[i].z);
            *(float2*)&s_xd[kb + 3][2 * lrow] = make_float2(xr[i].w, xr[i].w);
        }
        float4* sw4 = (float4*)s_w;
#pragma unroll
        for (int i = 0; i < 2; i++) sw4[t + 256 * i] = wr[i];
        __syncthreads();

        // prefetch next tile
        if (kt + 1 < NT) {
            const float4* xgn = xg + (size_t)(kt + 1) * 8;
            const float4* wgn = wg + (size_t)(kt + 1) * 512;
#pragma unroll
            for (int i = 0; i < 2; i++) xr[i] = xgn[i];
#pragma unroll
            for (int i = 0; i < 2; i++) wr[i] = wgn[t + 256 * i];
        }

        // compute: 2 rows x 8 experts per thread, f32x2-packed along experts
#pragma unroll 16
        for (int kk = 0; kk < K_TILE; ++kk) {
            ulonglong2 xa = *(const ulonglong2*)&s_xd[kk][2 * r0];
            ulonglong2 wa = *(const ulonglong2*)&s_w[kk * E + elo];
            ulonglong2 wb = *(const ulonglong2*)&s_w[kk * E + elo + 32];
            ffma2(acc[0][0], xa.x, wa.x); ffma2(acc[0][1], xa.x, wa.y);
            ffma2(acc[0][2], xa.x, wb.x); ffma2(acc[0][3], xa.x, wb.y);
            ffma2(acc[1][0], xa.y, wa.x); ffma2(acc[1][1], xa.y, wa.y);
            ffma2(acc[1][2], xa.y, wb.x); ffma2(acc[1][3], xa.y, wb.y);
        }
    }

    // finalize row stats (4 loader threads per row)
    sum   += __shfl_xor_sync(0xffffffffu, sum, 1);
    sumsq += __shfl_xor_sync(0xffffffffu, sumsq, 1);
    sum   += __shfl_xor_sync(0xffffffffu, sum, 2);
    sumsq += __shfl_xor_sync(0xffffffffu, sumsq, 2);
    if ((t & 3) == 0) {
        float mu  = sum * (1.0f / H);
        float var = sumsq * (1.0f / H) - mu * mu;
        s_mu[lrow]   = mu;
        s_rstd[lrow] = 1.0f / sqrtf(var + 1e-5f);
    }
    __syncthreads();

    float* out_p = out;                         // (N,2) normalized top-2 probs
    float* out_i = out + (size_t)n_rows * 2;    // (N,2) indices (as float)
    float* out_l = out + (size_t)n_rows * 4;    // (N,64) logits

#pragma unroll
    for (int j = 0; j < 2; j++) {
        int row  = r0 + j;
        int grow = row_base + row;
        float mu   = s_mu[row];
        float rstd = s_rstd[row];
        float l[8];
#pragma unroll
        for (int p = 0; p < 4; p++) {
            unsigned long long v = acc[j][p];
            l[2 * p]     = __uint_as_float((unsigned int)(v & 0xffffffffull));
            l[2 * p + 1] = __uint_as_float((unsigned int)(v >> 32));
        }
#pragma unroll
        for (int i = 0; i < 8; i++) {
            int e = (i < 4) ? (elo + i) : (32 + elo + (i - 4));
            float lv = rstd * (l[i] - mu * s_c[e]) + s_d[e];
            l[i] = fminf(fmaxf(lv, -10.0f), 10.0f);
        }
        *(float4*)&out_l[(size_t)grow * 64 + elo]      = make_float4(l[0], l[1], l[2], l[3]);
        *(float4*)&out_l[(size_t)grow * 64 + 32 + elo] = make_float4(l[4], l[5], l[6], l[7]);

        // row max over 64 (8 local + width-8 butterfly over tx)
        float m = l[0];
#pragma unroll
        for (int i = 1; i < 8; i++) m = fmaxf(m, l[i]);
#pragma unroll
        for (int s8 = 4; s8; s8 >>= 1)
            m = fmaxf(m, __shfl_xor_sync(0xffffffffu, m, s8));

        float ev[8];
        float s = 0.f;
#pragma unroll
        for (int i = 0; i < 8; i++) { ev[i] = expf(l[i] - m); s += ev[i]; }
#pragma unroll
        for (int s8 = 4; s8; s8 >>= 1)
            s += __shfl_xor_sync(0xffffffffu, s, s8);

        // local top-2 (clip to [1e-4, 1] first, as reference does before top_k)
        float v1 = -1.f, v2 = -1.f; int i1 = 0, i2 = 0;
#pragma unroll
        for (int i = 0; i < 8; i++) {
            float p = ev[i] / s;
            p = fminf(fmaxf(p, 1e-4f), 1.0f);
            int gi = (i < 4) ? (elo + i) : (32 + elo + (i - 4));
            if (p > v1 || (p == v1 && gi < i1)) { v2 = v1; i2 = i1; v1 = p; i1 = gi; }
            else if (p > v2 || (p == v2 && gi < i2)) { v2 = p; i2 = gi; }
        }
        // butterfly merge of top-2 lists, tie-break on lower index (jax top_k)
#pragma unroll
        for (int s8 = 4; s8; s8 >>= 1) {
            float u1 = __shfl_xor_sync(0xffffffffu, v1, s8);
            int   j1 = __shfl_xor_sync(0xffffffffu, i1, s8);
            float u2 = __shfl_xor_sync(0xffffffffu, v2, s8);
            int   j2 = __shfl_xor_sync(0xffffffffu, i2, s8);
            bool afirst = (v1 > u1) || (v1 == u1 && i1 < j1);
            float w1 = afirst ? v1 : u1;  int k1 = afirst ? i1 : j1;
            float ca = afirst ? v2 : u2;  int kca = afirst ? i2 : j2;  // winner's 2nd
            float cb = afirst ? u1 : v1;  int kcb = afirst ? j1 : i1;  // loser's 1st
            bool bsec = (cb > ca) || (cb == ca && kcb < kca);
            float w2 = bsec ? cb : ca;    int k2 = bsec ? kcb : kca;
            v1 = w1; i1 = k1; v2 = w2; i2 = k2;
        }
        if (tx == 0) {
            float ps = fmaxf(v1 + v2, 1e-4f);
            out_p[(size_t)grow * 2 + 0] = v1 / ps;
            out_p[(size_t)grow * 2 + 1] = v2 / ps;
            out_i[(size_t)grow * 2 + 0] = (float)i1;
            out_i[(size_t)grow * 2 + 1] = (float)i2;
        }
    }
}

extern "C" void kernel_launch(void* const* d_in, const int* in_sizes, int n_in,
                              void* d_out, int out_size) {
    const float* X = (const float*)d_in[0];   // hidden_states (4,4096,2048)
    const float* w = (const float*)d_in[1];   // ln_weight (2048)
    const float* b = (const float*)d_in[2];   // ln_bias (2048)
    const float* g = (const float*)d_in[3];   // gate_weight (64,2048)
    int n_rows = in_sizes[0] / H;             // 16384

    prep_kernel<<<E, 256>>>(g, w, b);
    router_kernel<<<n_rows / M_TILE, NTHREADS>>>(X, (float*)d_out, n_rows);
}

// round 6
// speedup vs baseline: 1.0062x; 1.0062x over previous
#include <cuda_runtime.h>

#define H        2048
#define E        64
#define M_TILE   128
#define K_TILE   32
#define NTHREADS 256

// Prep-kernel outputs (static device scratch; no allocations allowed)
__device__ float g_wgT[H * E];   // [h][e] = gate[e][h] * ln_weight[h]
__device__ float g_c[E];         // sum_h gate[e][h]*w[h]
__device__ float g_d[E];         // sum_h ln_bias[h]*gate[e][h]

// ---------------------------------------------------------------------------
// prep: build transposed, ln_weight-folded gate matrix + per-expert constants
// ---------------------------------------------------------------------------
__global__ void prep_kernel(const float* __restrict__ gate,
                            const float* __restrict__ w,
                            const float* __restrict__ b) {
    int e = blockIdx.x;
    int t = threadIdx.x;
    float sc = 0.f, sd = 0.f;
    for (int h = t; h < H; h += 256) {
        float gv = gate[e * H + h];
        float p  = gv * w[h];
        g_wgT[h * E + e] = p;
        sc += p;
        sd += b[h] * gv;
    }
    __shared__ float rs[256], rd[256];
    rs[t] = sc; rd[t] = sd;
    __syncthreads();
    for (int s = 128; s > 0; s >>= 1) {
        if (t < s) { rs[t] += rs[t + s]; rd[t] += rd[t + s]; }
        __syncthreads();
    }
    if (t == 0) { g_c[e] = rs[0]; g_d[e] = rd[0]; }
}

// packed f32x2 FMA (Blackwell): d = a*b + d elementwise on float pairs
__device__ __forceinline__ void ffma2(unsigned long long& d,
                                      unsigned long long a,
                                      unsigned long long b) {
    asm("fma.rn.f32x2 %0, %1, %2, %0;" : "+l"(d) : "l"(a), "l"(b));
}

// ---------------------------------------------------------------------------
// main: fused stats + GEMM + softmax + top2
// grid = n_rows/128 blocks, 256 threads
// thread tile = 8 rows x 4 experts; acc pairs packed along ROWS so x needs no
// duplication in smem; weights (small) are duplicated instead.
// layout: tx = t&15 (expert group, e0=4*tx), tyg = t>>4 (row group, r0=8*tyg)
// ---------------------------------------------------------------------------
__global__ __launch_bounds__(NTHREADS)
void router_kernel(const float* __restrict__ X, float* __restrict__ out,
                   int n_rows) {
    __shared__ float s_x[K_TILE][M_TILE];       // 16 KB (x stored once)
    __shared__ float s_wd[K_TILE][2 * E];       // 16 KB (weights duplicated)
    __shared__ float s_mu[M_TILE], s_rstd[M_TILE];
    __shared__ float s_c[E], s_d[E];

    const int t  = threadIdx.x;
    const int row_base = blockIdx.x * M_TILE;
    const int tx  = t & 15;      // expert group (0..15)
    const int tyg = t >> 4;      // row group (0..15)
    const int e0  = tx * 4;      // 4 experts per thread
    const int r0  = tyg * 8;     // 8 rows per thread

    if (t < E) { s_c[t] = g_c[t]; s_d[t] = g_d[t]; }

    // loader mapping: 2 threads per row, 16 consecutive floats each
    const int lrow = t >> 1;           // 0..127
    const int lk   = (t & 1) * 16;     // 0 or 16
    const float4* xg = (const float4*)(X + (size_t)(row_base + lrow) * H + lk);
    const float4* wg = (const float4*)g_wgT;   // tile kt starts at float4 idx kt*512

    float4 xr[4], wr[2];
#pragma unroll
    for (int i = 0; i < 4; i++) xr[i] = xg[i];
#pragma unroll
    for (int i = 0; i < 2; i++) wr[i] = wg[t + 256 * i];

    unsigned long long acc[4][4];   // [expert][rowpair]
#pragma unroll
    for (int e = 0; e < 4; e++)
#pragma unroll
        for (int rp = 0; rp < 4; rp++) acc[e][rp] = 0ull;

    float sum = 0.f, sumsq = 0.f;

    const int NT = H / K_TILE;  // 64
    for (int kt = 0; kt < NT; ++kt) {
        // row stats from the registers we're about to store
#pragma unroll
        for (int i = 0; i < 4; i++) {
            sum   += xr[i].x + xr[i].y + xr[i].z + xr[i].w;
            sumsq += xr[i].x * xr[i].x + xr[i].y * xr[i].y +
                     xr[i].z * xr[i].z + xr[i].w * xr[i].w;
        }
        __syncthreads();
        // store x (k-transposed, single copy)
#pragma unroll
        for (int i = 0; i < 4; i++) {
            int kb = lk + 4 * i;
            s_x[kb + 0][lrow] = xr[i].x;
            s_x[kb + 1][lrow] = xr[i].y;
            s_x[kb + 2][lrow] = xr[i].z;
            s_x[kb + 3][lrow] = xr[i].w;
        }
        // store weights duplicated: element (kk, e) -> s_wd[kk][2e], [2e+1]
#pragma unroll
        for (int i = 0; i < 2; i++) {
            int lin = (t + 256 * i) * 4;    // float index within 32x64 tile
            int kk  = lin >> 6;
            int e   = lin & 63;
            float4 v = wr[i];
            *(float2*)&s_wd[kk][2 * e + 0] = make_float2(v.x, v.x);
            *(float2*)&s_wd[kk][2 * e + 2] = make_float2(v.y, v.y);
            *(float2*)&s_wd[kk][2 * e + 4] = make_float2(v.z, v.z);
            *(float2*)&s_wd[kk][2 * e + 6] = make_float2(v.w, v.w);
        }
        __syncthreads();

        // prefetch next tile
        if (kt + 1 < NT) {
            const float4* xgn = xg + (size_t)(kt + 1) * 8;
            const float4* wgn = wg + (size_t)(kt + 1) * 512;
#pragma unroll
            for (int i = 0; i < 4; i++) xr[i] = xgn[i];
#pragma unroll
            for (int i = 0; i < 2; i++) wr[i] = wgn[t + 256 * i];
        }

        // compute: 8 rows x 4 experts per thread, f32x2-packed along rows
#pragma unroll 16
        for (int kk = 0; kk < K_TILE; ++kk) {
            ulonglong2 xa = *(const ulonglong2*)&s_x[kk][r0];       // rows r0..r0+3
            ulonglong2 xb = *(const ulonglong2*)&s_x[kk][r0 + 4];   // rows r0+4..r0+7
            ulonglong2 wa = *(const ulonglong2*)&s_wd[kk][2 * e0];      // e0, e0+1 (dup)
            ulonglong2 wb = *(const ulonglong2*)&s_wd[kk][2 * e0 + 4];  // e0+2, e0+3
            ffma2(acc[0][0], xa.x, wa.x); ffma2(acc[0][1], xa.y, wa.x);
            ffma2(acc[0][2], xb.x, wa.x); ffma2(acc[0][3], xb.y, wa.x);
            ffma2(acc[1][0], xa.x, wa.y); ffma2(acc[1][1], xa.y, wa.y);
            ffma2(acc[1][2], xb.x, wa.y); ffma2(acc[1][3], xb.y, wa.y);
            ffma2(acc[2][0], xa.x, wb.x); ffma2(acc[2][1], xa.y, wb.x);
            ffma2(acc[2][2], xb.x, wb.x); ffma2(acc[2][3], xb.y, wb.x);
            ffma2(acc[3][0], xa.x, wb.y); ffma2(acc[3][1], xa.y, wb.y);
            ffma2(acc[3][2], xb.x, wb.y); ffma2(acc[3][3], xb.y, wb.y);
        }
    }

    // finalize row stats (2 loader threads per row)
    sum   += __shfl_xor_sync(0xffffffffu, sum, 1);
    sumsq += __shfl_xor_sync(0xffffffffu, sumsq, 1);
    if ((t & 1) == 0) {
        float mu  = sum * (1.0f / H);
        float var = sumsq * (1.0f / H) - mu * mu;
        s_mu[lrow]   = mu;
        s_rstd[lrow] = 1.0f / sqrtf(var + 1e-5f);
    }
    __syncthreads();

    float* out_p = out;                         // (N,2) normalized top-2 probs
    float* out_i = out + (size_t)n_rows * 2;    // (N,2) indices (as float)
    float* out_l = out + (size_t)n_rows * 4;    // (N,64) logits

#pragma unroll
    for (int rp = 0; rp < 4; rp++) {
#pragma unroll
        for (int half = 0; half < 2; half++) {
            int row  = r0 + 2 * rp + half;
            int grow = row_base + row;
            float mu   = s_mu[row];
            float rstd = s_rstd[row];
            float l[4];
#pragma unroll
            for (int e = 0; e < 4; e++) {
                unsigned long long v = acc[e][rp];
                unsigned int bits = half ? (unsigned int)(v >> 32)
                                         : (unsigned int)(v & 0xffffffffull);
                float lv = rstd * (__uint_as_float(bits) - mu * s_c[e0 + e]) + s_d[e0 + e];
                l[e] = fminf(fmaxf(lv, -10.0f), 10.0f);
            }
            *(float4*)&out_l[(size_t)grow * 64 + e0] = make_float4(l[0], l[1], l[2], l[3]);

            // row max over 64 (4 local + width-16 butterfly over tx)
            float m = fmaxf(fmaxf(l[0], l[1]), fmaxf(l[2], l[3]));
#pragma unroll
            for (int s16 = 8; s16; s16 >>= 1)
                m = fmaxf(m, __shfl_xor_sync(0xffffffffu, m, s16));

            float ev[4];
            float s = 0.f;
#pragma unroll
            for (int e = 0; e < 4; e++) { ev[e] = expf(l[e] - m); s += ev[e]; }
#pragma unroll
            for (int s16 = 8; s16; s16 >>= 1)
                s += __shfl_xor_sync(0xffffffffu, s, s16);

            // local top-2 (clip to [1e-4, 1] first, as reference does)
            float v1 = -1.f, v2 = -1.f; int i1 = 0, i2 = 0;
#pragma unroll
            for (int e = 0; e < 4; e++) {
                float p = ev[e] / s;
                p = fminf(fmaxf(p, 1e-4f), 1.0f);
                int gi = e0 + e;
                if (p > v1) { v2 = v1; i2 = i1; v1 = p; i1 = gi; }
                else if (p > v2) { v2 = p; i2 = gi; }
            }
            // butterfly merge of top-2 lists, tie-break on lower index
#pragma unroll
            for (int s16 = 8; s16; s16 >>= 1) {
                float u1 = __shfl_xor_sync(0xffffffffu, v1, s16);
                int   j1 = __shfl_xor_sync(0xffffffffu, i1, s16);
                float u2 = __shfl_xor_sync(0xffffffffu, v2, s16);
                int   j2 = __shfl_xor_sync(0xffffffffu, i2, s16);
                bool afirst = (v1 > u1) || (v1 == u1 && i1 < j1);
                float w1 = afirst ? v1 : u1;  int k1 = afirst ? i1 : j1;
                float ca = afirst ? v2 : u2;  int kca = afirst ? i2 : j2;  // winner's 2nd
                float cb = afirst ? u1 : v1;  int kcb = afirst ? j1 : i1;  // loser's 1st
                bool bsec = (cb > ca) || (cb == ca && kcb < kca);
                float w2 = bsec ? cb : ca;    int k2 = bsec ? kcb : kca;
                v1 = w1; i1 = k1; v2 = w2; i2 = k2;
            }
            if (tx == 0) {
                float ps = fmaxf(v1 + v2, 1e-4f);
                out_p[(size_t)grow * 2 + 0] = v1 / ps;
                out_p[(size_t)grow * 2 + 1] = v2 / ps;
                out_i[(size_t)grow * 2 + 0] = (float)i1;
                out_i[(size_t)grow * 2 + 1] = (float)i2;
            }
        }
    }
}

extern "C" void kernel_launch(void* const* d_in, const int* in_sizes, int n_in,
                              void* d_out, int out_size) {
    const float* X = (const float*)d_in[0];   // hidden_states (4,4096,2048)
    const float* w = (const float*)d_in[1];   // ln_weight (2048)
    const float* b = (const float*)d_in[2];   // ln_bias (2048)
    const float* g = (const float*)d_in[3];   // gate_weight (64,2048)
    int n_rows = in_sizes[0] / H;             // 16384

    prep_kernel<<<E, 256>>>(g, w, b);
    router_kernel<<<n_rows / M_TILE, NTHREADS>>>(X, (float*)d_out, n_rows);
}

// round 7
// speedup vs baseline: 1.6230x; 1.6129x over previous
#include <cuda_runtime.h>
#include <cstdint>

#define H        2048
#define E        64
#define M_TILE   128
#define NT       64      // k tiles of 32
#define NTHREADS 128

// Prep outputs (static device scratch)
__device__ float g_wp[H * E];   // permuted: chunk(kt,kb, i=e&7, tx=e>>3)[kq]
__device__ float g_c[E];        // sum_h gate[e][h]*w[h]
__device__ float g_d[E];        // sum_h ln_bias[h]*gate[e][h]

// ---------------------------------------------------------------------------
// prep: fold ln_weight into gate, permute for conflict-free compute loads
// element (e, k) -> g_wp[(((k>>5)*8 + ((k>>2)&7))*64 + (e&7)*8 + (e>>3))*4 + (k&3)]
// ---------------------------------------------------------------------------
__global__ void prep_kernel(const float* __restrict__ gate,
                            const float* __restrict__ w,
                            const float* __restrict__ b) {
    int e = blockIdx.x;
    int t = threadIdx.x;
    int ei = e & 7, txe = e >> 3;
    float sc = 0.f, sd = 0.f;
    for (int k = t; k < H; k += 256) {
        float gv = gate[e * H + k];
        float p  = gv * w[k];
        int kt = k >> 5, kb = (k >> 2) & 7, kq = k & 3;
        g_wp[(((kt * 8 + kb) * 64) + ei * 8 + txe) * 4 + kq] = p;
        sc += p;
        sd += b[k] * gv;
    }
    __shared__ float rs[256], rd[256];
    rs[t] = sc; rd[t] = sd;
    __syncthreads();
    for (int s = 128; s > 0; s >>= 1) {
        if (t < s) { rs[t] += rs[t + s]; rd[t] += rd[t + s]; }
        __syncthreads();
    }
    if (t == 0) { g_c[e] = rs[0]; g_d[e] = rd[0]; }
}

// packed f32x2 FMA (Blackwell): d = a*b + d elementwise on float pairs
__device__ __forceinline__ void ffma2(unsigned long long& d,
                                      unsigned long long a,
                                      unsigned long long b) {
    asm("fma.rn.f32x2 %0, %1, %2, %0;" : "+l"(d) : "l"(a), "l"(b));
}

// ---------------------------------------------------------------------------
// main: fused stats + GEMM (k-packed f32x2) + softmax + top2
// grid = 128 blocks x 128 threads; thread tile = 8 rows x 8 experts
// tx = t&7 -> experts [8tx, 8tx+8);  r0 = (t>>3)*8 -> rows [r0, r0+8)
// x smem: slot = kb*128 + (row ^ kb)     (broadcast reads, conflict-free STS)
// w smem: slot = kb*64 + (e&7)*8 + (e>>3) (phase-consecutive reads)
// ---------------------------------------------------------------------------
__global__ __launch_bounds__(NTHREADS, 1)
void router_kernel(const float* __restrict__ X, float* __restrict__ out,
                   int n_rows) {
    __shared__ float4 s_x[8 * 128];        // 16 KB
    __shared__ float4 s_w[2][8 * 64];      // 2 x 8 KB (cp.async double buffer)
    __shared__ float s_mu[M_TILE], s_rstd[M_TILE];

    const int t = threadIdx.x;
    const int row_base = blockIdx.x * M_TILE;
    const int tx = t & 7;
    const int r0 = (t >> 3) * 8;
    const int lrow = t >> 2;       // loader: 0..31
    const int lkq  = t & 3;        // loader: k segment (8 floats)

    uint32_t w_smem0 = (uint32_t)__cvta_generic_to_shared(&s_w[0][0]);
    uint32_t w_smem1 = (uint32_t)__cvta_generic_to_shared(&s_w[1][0]);

    const float* xg0 = X + (size_t)(row_base + lrow) * H + lkq * 8;

    unsigned long long acc[8][8];
#pragma unroll
    for (int a = 0; a < 8; a++)
#pragma unroll
        for (int b2 = 0; b2 < 8; b2++) acc[a][b2] = 0ull;

    float st_s[4] = {0.f, 0.f, 0.f, 0.f};
    float st_q[4] = {0.f, 0.f, 0.f, 0.f};
    float4 xs[4][2];

    // prologue: w tile 0 via cp.async, x tile 0 via LDG
    {
        const float* wsrc = g_wp + t * 4;
#pragma unroll
        for (int c = 0; c < 4; c++) {
            asm volatile("cp.async.cg.shared.global [%0], [%1], 16;\n"
                         :: "r"(w_smem0 + (t + 128 * c) * 16), "l"(wsrc + 512 * c));
        }
        asm volatile("cp.async.commit_group;\n" ::: "memory");
#pragma unroll
        for (int p = 0; p < 4; p++)
#pragma unroll
            for (int q = 0; q < 2; q++)
                xs[p][q] = *(const float4*)(xg0 + (size_t)p * 32 * H + q * 4);
    }

    for (int kt = 0; kt < NT; ++kt) {
        __syncthreads();
        // store x tile kt (swizzled) + accumulate LN stats from registers
#pragma unroll
        for (int p = 0; p < 4; p++) {
#pragma unroll
            for (int q = 0; q < 2; q++) {
                int kb = 2 * lkq + q;
                s_x[kb * 128 + ((lrow ^ kb) + 32 * p)] = xs[p][q];
                float4 v = xs[p][q];
                st_s[p] += (v.x + v.y) + (v.z + v.w);
                st_q[p] += v.x * v.x + v.y * v.y + v.z * v.z + v.w * v.w;
            }
        }
        // prefetch next tile: w -> other smem buffer, x -> registers
        if (kt + 1 < NT) {
            const float* wsrc = g_wp + (size_t)(kt + 1) * 2048 + t * 4;
            uint32_t wbase = ((kt + 1) & 1) ? w_smem1 : w_smem0;
#pragma unroll
            for (int c = 0; c < 4; c++) {
                asm volatile("cp.async.cg.shared.global [%0], [%1], 16;\n"
                             :: "r"(wbase + (t + 128 * c) * 16), "l"(wsrc + 512 * c));
            }
            asm volatile("cp.async.commit_group;\n" ::: "memory");
            const float* xgn = xg0 + (size_t)(kt + 1) * 32;
#pragma unroll
            for (int p = 0; p < 4; p++)
#pragma unroll
                for (int q = 0; q < 2; q++)
                    xs[p][q] = *(const float4*)(xgn + (size_t)p * 32 * H + q * 4);
            asm volatile("cp.async.wait_group 1;\n" ::: "memory");
        } else {
            asm volatile("cp.async.wait_group 0;\n" ::: "memory");
        }
        __syncthreads();

        // compute: 8 steps of 4 k; 16 LDS.128 + 128 FFMA2 per step
        const float4* wb = s_w[kt & 1];
#pragma unroll
        for (int kb = 0; kb < 8; kb++) {
            ulonglong2 xv[8], wv[8];
#pragma unroll
            for (int i = 0; i < 8; i++)
                xv[i] = *(const ulonglong2*)&s_x[kb * 128 + r0 + (i ^ kb)];
#pragma unroll
            for (int i = 0; i < 8; i++)
                wv[i] = *(const ulonglong2*)&wb[kb * 64 + i * 8 + tx];
#pragma unroll
            for (int ei = 0; ei < 8; ei++)
#pragma unroll
                for (int ri = 0; ri < 8; ri++) {
                    ffma2(acc[ei][ri], xv[ri].x, wv[ei].x);
                    ffma2(acc[ei][ri], xv[ri].y, wv[ei].y);
                }
        }
    }

    // finalize LN stats (loader partners: lanes differing in bits 0-1)
#pragma unroll
    for (int p = 0; p < 4; p++) {
        float s = st_s[p], qq = st_q[p];
        s  += __shfl_xor_sync(0xffffffffu, s, 1);
        qq += __shfl_xor_sync(0xffffffffu, qq, 1);
        s  += __shfl_xor_sync(0xffffffffu, s, 2);
        qq += __shfl_xor_sync(0xffffffffu, qq, 2);
        if (lkq == 0) {
            float mu  = s * (1.0f / H);
            float var = qq * (1.0f / H) - mu * mu;
            s_mu[lrow + 32 * p]   = mu;
            s_rstd[lrow + 32 * p] = rsqrtf(var + 1e-5f);
        }
    }
    __syncthreads();

    float cc[8], dd[8];
#pragma unroll
    for (int i = 0; i < 8; i++) { cc[i] = g_c[8 * tx + i]; dd[i] = g_d[8 * tx + i]; }

    float* out_p = out;                         // (N,2) normalized top-2 probs
    float* out_i = out + (size_t)n_rows * 2;    // (N,2) indices (as float)
    float* out_l = out + (size_t)n_rows * 4;    // (N,64) logits

#pragma unroll
    for (int ri = 0; ri < 8; ri++) {
        int row  = r0 + ri;
        int grow = row_base + row;
        float mu   = s_mu[row];
        float rstd = s_rstd[row];
        float l[8];
#pragma unroll
        for (int ei = 0; ei < 8; ei++) {
            unsigned long long v = acc[ei][ri];
            float lv = __uint_as_float((unsigned int)(v & 0xffffffffull)) +
                       __uint_as_float((unsigned int)(v >> 32));
            lv = rstd * (lv - mu * cc[ei]) + dd[ei];
            l[ei] = fminf(fmaxf(lv, -10.0f), 10.0f);
        }
        *(float4*)&out_l[(size_t)grow * 64 + 8 * tx]     = make_float4(l[0], l[1], l[2], l[3]);
        *(float4*)&out_l[(size_t)grow * 64 + 8 * tx + 4] = make_float4(l[4], l[5], l[6], l[7]);

        // row max over 64 (8 local + width-8 butterfly over tx)
        float m = l[0];
#pragma unroll
        for (int i = 1; i < 8; i++) m = fmaxf(m, l[i]);
#pragma unroll
        for (int s8 = 4; s8; s8 >>= 1)
            m = fmaxf(m, __shfl_xor_sync(0xffffffffu, m, s8));

        float ev[8];
        float s = 0.f;
#pragma unroll
        for (int i = 0; i < 8; i++) { ev[i] = expf(l[i] - m); s += ev[i]; }
#pragma unroll
        for (int s8 = 4; s8; s8 >>= 1)
            s += __shfl_xor_sync(0xffffffffu, s, s8);

        // local top-2 (clip to [1e-4, 1] first, as reference does)
        float v1 = -1.f, v2 = -1.f; int i1 = 0, i2 = 0;
#pragma unroll
        for (int i = 0; i < 8; i++) {
            float p = ev[i] / s;
            p = fminf(fmaxf(p, 1e-4f), 1.0f);
            int gi = 8 * tx + i;
            if (p > v1) { v2 = v1; i2 = i1; v1 = p; i1 = gi; }
            else if (p > v2) { v2 = p; i2 = gi; }
        }
        // butterfly merge of top-2 lists, tie-break on lower index (jax top_k)
#pragma unroll
        for (int s8 = 4; s8; s8 >>= 1) {
            float u1 = __shfl_xor_sync(0xffffffffu, v1, s8);
            int   j1 = __shfl_xor_sync(0xffffffffu, i1, s8);
            float u2 = __shfl_xor_sync(0xffffffffu, v2, s8);
            int   j2 = __shfl_xor_sync(0xffffffffu, i2, s8);
            bool afirst = (v1 > u1) || (v1 == u1 && i1 < j1);
            float w1 = afirst ? v1 : u1;  int k1 = afirst ? i1 : j1;
            float ca = afirst ? v2 : u2;  int kca = afirst ? i2 : j2;  // winner's 2nd
            float cb = afirst ? u1 : v1;  int kcb = afirst ? j1 : i1;  // loser's 1st
            bool bsec = (cb > ca) || (cb == ca && kcb < kca);
            float w2 = bsec ? cb : ca;    int k2 = bsec ? kcb : kca;
            v1 = w1; i1 = k1; v2 = w2; i2 = k2;
        }
        if (tx == 0) {
            float ps = fmaxf(v1 + v2, 1e-4f);
            out_p[(size_t)grow * 2 + 0] = v1 / ps;
            out_p[(size_t)grow * 2 + 1] = v2 / ps;
            out_i[(size_t)grow * 2 + 0] = (float)i1;
            out_i[(size_t)grow * 2 + 1] = (float)i2;
        }
    }
}

extern "C" void kernel_launch(void* const* d_in, const int* in_sizes, int n_in,
                              void* d_out, int out_size) {
    const float* X = (const float*)d_in[0];   // hidden_states (4,4096,2048)
    const float* w = (const float*)d_in[1];   // ln_weight (2048)
    const float* b = (const float*)d_in[2];   // ln_bias (2048)
    const float* g = (const float*)d_in[3];   // gate_weight (64,2048)
    int n_rows = in_sizes[0] / H;             // 16384

    prep_kernel<<<E, 256>>>(g, w, b);
    router_kernel<<<n_rows / M_TILE, NTHREADS>>>(X, (float*)d_out, n_rows);
}

// round 9
// speedup vs baseline: 1.7823x; 1.0982x over previous
#include <cuda_runtime.h>
#include <cstdint>

#define H        2048
#define E        64
#define M_TILE   128
#define NT       64      // k tiles of 32
#define NTHREADS 256

// Prep outputs (static device scratch)
__device__ float g_wp[H * E];   // permuted: chunk(kt,kb, i=e&7, tx=e>>3)[kq]
__device__ float g_c[E];        // sum_h gate[e][h]*w[h]
__device__ float g_d[E];        // sum_h ln_bias[h]*gate[e][h]

// ---------------------------------------------------------------------------
// prep: fold ln_weight into gate, permute for conflict-free compute loads
// element (e, k) -> g_wp[(((k>>5)*8 + ((k>>2)&7))*64 + (e&7)*8 + (e>>3))*4 + (k&3)]
// ---------------------------------------------------------------------------
__global__ void prep_kernel(const float* __restrict__ gate,
                            const float* __restrict__ w,
                            const float* __restrict__ b) {
    int e = blockIdx.x;
    int t = threadIdx.x;
    int ei = e & 7, txe = e >> 3;
    float sc = 0.f, sd = 0.f;
    for (int k = t; k < H; k += 256) {
        float gv = gate[e * H + k];
        float p  = gv * w[k];
        int kt = k >> 5, kb = (k >> 2) & 7, kq = k & 3;
        g_wp[(((kt * 8 + kb) * 64) + ei * 8 + txe) * 4 + kq] = p;
        sc += p;
        sd += b[k] * gv;
    }
    __shared__ float rs[256], rd[256];
    rs[t] = sc; rd[t] = sd;
    __syncthreads();
    for (int s = 128; s > 0; s >>= 1) {
        if (t < s) { rs[t] += rs[t + s]; rd[t] += rd[t + s]; }
        __syncthreads();
    }
    if (t == 0) { g_c[e] = rs[0]; g_d[e] = rd[0]; }
}

// packed f32x2 FMA (Blackwell): d = a*b + d elementwise on float pairs
__device__ __forceinline__ void ffma2(unsigned long long& d,
                                      unsigned long long a,
                                      unsigned long long b) {
    asm("fma.rn.f32x2 %0, %1, %2, %0;" : "+l"(d) : "l"(a), "l"(b));
}

// ---------------------------------------------------------------------------
// main: fused stats + GEMM (k-packed f32x2) + softmax + top2
// grid = 128 blocks x 256 threads; thread tile = 4 rows x 8 experts
// tx = t&7 -> experts [8tx, 8tx+8);  r0 = (t>>3)*4 -> rows [r0, r0+4)
// x smem: slot = kb*128 + (row ^ kb)     (broadcast reads, conflict-free STS)
// w smem: slot = kb*64 + (e&7)*8 + (e>>3) (phase-consecutive reads)
// ---------------------------------------------------------------------------
__global__ __launch_bounds__(NTHREADS, 1)
void router_kernel(const float* __restrict__ X, float* __restrict__ out,
                   int n_rows) {
    __shared__ float4 s_x[8 * 128];        // 16 KB
    __shared__ float4 s_w[2][8 * 64];      // 2 x 8 KB (cp.async double buffer)
    __shared__ float s_mu[M_TILE], s_rstd[M_TILE];

    const int t = threadIdx.x;
    const int row_base = blockIdx.x * M_TILE;
    const int tx = t & 7;
    const int r0 = (t >> 3) * 4;
    const int lrow = t >> 2;       // loader: 0..63 (rows lrow, lrow+64)
    const int lkq  = t & 3;        // loader: k segment (8 floats)

    uint32_t w_smem0 = (uint32_t)__cvta_generic_to_shared(&s_w[0][0]);
    uint32_t w_smem1 = (uint32_t)__cvta_generic_to_shared(&s_w[1][0]);

    const float* xg0 = X + (size_t)(row_base + lrow) * H + lkq * 8;

    unsigned long long acc[8][4];
#pragma unroll
    for (int a = 0; a < 8; a++)
#pragma unroll
        for (int b2 = 0; b2 < 4; b2++) acc[a][b2] = 0ull;

    float st_s[2] = {0.f, 0.f};
    float st_q[2] = {0.f, 0.f};
    float4 xs[2][2];

    // prologue: w tile 0 via cp.async, x tile 0 via LDG
    {
        const float* wsrc = g_wp + t * 4;
#pragma unroll
        for (int c = 0; c < 2; c++) {
            asm volatile("cp.async.cg.shared.global [%0], [%1], 16;\n"
                         :: "r"(w_smem0 + (t + 256 * c) * 16), "l"(wsrc + 1024 * c));
        }
        asm volatile("cp.async.commit_group;\n" ::: "memory");
#pragma unroll
        for (int p = 0; p < 2; p++)
#pragma unroll
            for (int q = 0; q < 2; q++)
                xs[p][q] = *(const float4*)(xg0 + (size_t)p * 64 * H + q * 4);
    }

    for (int kt = 0; kt < NT; ++kt) {
        __syncthreads();
        // store x tile kt (swizzled) + accumulate LN stats from registers
#pragma unroll
        for (int p = 0; p < 2; p++) {
#pragma unroll
            for (int q = 0; q < 2; q++) {
                int kb = 2 * lkq + q;
                int row = lrow + 64 * p;
                s_x[kb * 128 + (row ^ kb)] = xs[p][q];
                float4 v = xs[p][q];
                st_s[p] += (v.x + v.y) + (v.z + v.w);
                st_q[p] += v.x * v.x + v.y * v.y + v.z * v.z + v.w * v.w;
            }
        }
        // prefetch next tile: w -> other smem buffer, x -> registers
        if (kt + 1 < NT) {
            const float* wsrc = g_wp + (size_t)(kt + 1) * 2048 + t * 4;
            uint32_t wbase = ((kt + 1) & 1) ? w_smem1 : w_smem0;
#pragma unroll
            for (int c = 0; c < 2; c++) {
                asm volatile("cp.async.cg.shared.global [%0], [%1], 16;\n"
                             :: "r"(wbase + (t + 256 * c) * 16), "l"(wsrc + 1024 * c));
            }
            asm volatile("cp.async.commit_group;\n" ::: "memory");
            const float* xgn = xg0 + (size_t)(kt + 1) * 32;
#pragma unroll
            for (int p = 0; p < 2; p++)
#pragma unroll
                for (int q = 0; q < 2; q++)
                    xs[p][q] = *(const float4*)(xgn + (size_t)p * 64 * H + q * 4);
            asm volatile("cp.async.wait_group 1;\n" ::: "memory");
        } else {
            asm volatile("cp.async.wait_group 0;\n" ::: "memory");
        }
        __syncthreads();

        // compute: 8 steps of 4 k; 12 LDS.128 + 64 FFMA2 per step per thread
        const float4* wb = s_w[kt & 1];
#pragma unroll
        for (int kb = 0; kb < 8; kb++) {
            ulonglong2 xv[4], wv[8];
            const int rbase = (r0 ^ (kb & 4));   // bit2 of row xor'd by kb bit2
#pragma unroll
            for (int i = 0; i < 4; i++)
                xv[i] = *(const ulonglong2*)&s_x[kb * 128 + rbase + (i ^ (kb & 3))];
#pragma unroll
            for (int i = 0; i < 8; i++)
                wv[i] = *(const ulonglong2*)&wb[kb * 64 + i * 8 + tx];
#pragma unroll
            for (int ei = 0; ei < 8; ei++)
#pragma unroll
                for (int ri = 0; ri < 4; ri++) {
                    ffma2(acc[ei][ri], xv[ri].x, wv[ei].x);
                    ffma2(acc[ei][ri], xv[ri].y, wv[ei].y);
                }
        }
    }

    // finalize LN stats (loader partners: lanes differing in bits 0-1)
#pragma unroll
    for (int p = 0; p < 2; p++) {
        float s = st_s[p], qq = st_q[p];
        s  += __shfl_xor_sync(0xffffffffu, s, 1);
        qq += __shfl_xor_sync(0xffffffffu, qq, 1);
        s  += __shfl_xor_sync(0xffffffffu, s, 2);
        qq += __shfl_xor_sync(0xffffffffu, qq, 2);
        if (lkq == 0) {
            float mu  = s * (1.0f / H);
            float var = qq * (1.0f / H) - mu * mu;
            s_mu[lrow + 64 * p]   = mu;
            s_rstd[lrow + 64 * p] = rsqrtf(var + 1e-5f);
        }
    }
    __syncthreads();

    float cc[8], dd[8];
#pragma unroll
    for (int i = 0; i < 8; i++) { cc[i] = g_c[8 * tx + i]; dd[i] = g_d[8 * tx + i]; }

    float* out_p = out;                         // (N,2) normalized top-2 probs
    float* out_i = out + (size_t)n_rows * 2;    // (N,2) indices (as float)
    float* out_l = out + (size_t)n_rows * 4;    // (N,64) logits

#pragma unroll
    for (int ri = 0; ri < 4; ri++) {
        int row  = r0 + ri;
        int grow = row_base + row;
        float mu   = s_mu[row];
        float rstd = s_rstd[row];
        float l[8];
#pragma unroll
        for (int ei = 0; ei < 8; ei++) {
            unsigned long long v = acc[ei][ri];
            float lv = __uint_as_float((unsigned int)(v & 0xffffffffull)) +
                       __uint_as_float((unsigned int)(v >> 32));
            lv = rstd * (lv - mu * cc[ei]) + dd[ei];
            l[ei] = fminf(fmaxf(lv, -10.0f), 10.0f);
        }
        *(float4*)&out_l[(size_t)grow * 64 + 8 * tx]     = make_float4(l[0], l[1], l[2], l[3]);
        *(float4*)&out_l[(size_t)grow * 64 + 8 * tx + 4] = make_float4(l[4], l[5], l[6], l[7]);

        // row max over 64 (8 local + width-8 butterfly over tx)
        float m = l[0];
#pragma unroll
        for (int i = 1; i < 8; i++) m = fmaxf(m, l[i]);
#pragma unroll
        for (int s8 = 4; s8; s8 >>= 1)
            m = fmaxf(m, __shfl_xor_sync(0xffffffffu, m, s8));

        float ev[8];
        float s = 0.f;
#pragma unroll
        for (int i = 0; i < 8; i++) { ev[i] = expf(l[i] - m); s += ev[i]; }
#pragma unroll
        for (int s8 = 4; s8; s8 >>= 1)
            s += __shfl_xor_sync(0xffffffffu, s, s8);

        // local top-2 (clip to [1e-4, 1] first, as reference does)
        float v1 = -1.f, v2 = -1.f; int i1 = 0, i2 = 0;
#pragma unroll
        for (int i = 0; i < 8; i++) {
            float p = ev[i] / s;
            p = fminf(fmaxf(p, 1e-4f), 1.0f);
            int gi = 8 * tx + i;
            if (p > v1) { v2 = v1; i2 = i1; v1 = p; i1 = gi; }
            else if (p > v2) { v2 = p; i2 = gi; }
        }
        // butterfly merge of top-2 lists, tie-break on lower index (jax top_k)
#pragma unroll
        for (int s8 = 4; s8; s8 >>= 1) {
            float u1 = __shfl_xor_sync(0xffffffffu, v1, s8);
            int   j1 = __shfl_xor_sync(0xffffffffu, i1, s8);
            float u2 = __shfl_xor_sync(0xffffffffu, v2, s8);
            int   j2 = __shfl_xor_sync(0xffffffffu, i2, s8);
            bool afirst = (v1 > u1) || (v1 == u1 && i1 < j1);
            float w1 = afirst ? v1 : u1;  int k1 = afirst ? i1 : j1;
            float ca = afirst ? v2 : u2;  int kca = afirst ? i2 : j2;  // winner's 2nd
            float cb = afirst ? u1 : v1;  int kcb = afirst ? j1 : i1;  // loser's 1st
            bool bsec = (cb > ca) || (cb == ca && kcb < kca);
            float w2 = bsec ? cb : ca;    int k2 = bsec ? kcb : kca;
            v1 = w1; i1 = k1; v2 = w2; i2 = k2;
        }
        if (tx == 0) {
            float ps = fmaxf(v1 + v2, 1e-4f);
            out_p[(size_t)grow * 2 + 0] = v1 / ps;
            out_p[(size_t)grow * 2 + 1] = v2 / ps;
            out_i[(size_t)grow * 2 + 0] = (float)i1;
            out_i[(size_t)grow * 2 + 1] = (float)i2;
        }
    }
}

extern "C" void kernel_launch(void* const* d_in, const int* in_sizes, int n_in,
                              void* d_out, int out_size) {
    const float* X = (const float*)d_in[0];   // hidden_states (4,4096,2048)
    const float* w = (const float*)d_in[1];   // ln_weight (2048)
    const float* b = (const float*)d_in[2];   // ln_bias (2048)
    const float* g = (const float*)d_in[3];   // gate_weight (64,2048)
    int n_rows = in_sizes[0] / H;             // 16384

    prep_kernel<<<E, 256>>>(g, w, b);
    router_kernel<<<n_rows / M_TILE, NTHREADS>>>(X, (float*)d_out, n_rows);
}